// round 9
// baseline (speedup 1.0000x reference)
#include <cuda_runtime.h>
#include <cuda_fp16.h>
#include <math.h>
#include <stdint.h>

#define NN   4096
#define KF   512     // IN_F
#define CF   512     // OUT_F * N_HEADS
#define NH   8
#define OF   64

// ---- scratch (device globals; no allocation allowed) ----
__device__ __half   g_W16T[CF * KF];        // 512 KB  W transposed fp16 [c][k]
__device__ float    g_wst[16 * KF];         // 32 KB   ws_t[h*2+d][k] = sum_f W[k][h*64+f]*a[d*64+f]
__device__ __half   g_Whf16[(size_t)NN * CF]; // 4 MB  Wh fp16 [n][c]
__device__ __half   g_WhT[NH * OF * NN];    // 4 MB    values transposed [h][f][n]
__device__ unsigned g_bits[NN * 128];       // 2 MB    packed adj
__device__ float4   g_attrS[NH * NN];       // (src, Es/16, Es2/16, 0)
__device__ uint4    g_attrP[NH * (NN / 2)]; // per j-pair: (dst2, Ed2, Ed22, pad)

__device__ __forceinline__ uint32_t smem_u32(const void* p) {
    uint32_t a;
    asm("{ .reg .u64 t; cvta.to.shared.u64 t, %1; cvt.u32.u64 %0, t; }" : "=r"(a) : "l"(p));
    return a;
}
__device__ __forceinline__ unsigned h2u(__half2 v) {
    return *reinterpret_cast<unsigned*>(&v);
}
__device__ __forceinline__ void ldsm4(uint32_t& r0, uint32_t& r1, uint32_t& r2, uint32_t& r3,
                                      uint32_t addr) {
    asm volatile("ldmatrix.sync.aligned.m8n8.x4.shared.b16 {%0,%1,%2,%3}, [%4];"
                 : "=r"(r0), "=r"(r1), "=r"(r2), "=r"(r3) : "r"(addr));
}
__device__ __forceinline__ void mma16816(float* d, const uint32_t* a, const uint32_t* b) {
    asm volatile(
        "mma.sync.aligned.m16n8k16.row.col.f32.f16.f16.f32 "
        "{%0,%1,%2,%3}, {%4,%5,%6,%7}, {%8,%9}, {%0,%1,%2,%3};"
        : "+f"(d[0]), "+f"(d[1]), "+f"(d[2]), "+f"(d[3])
        : "r"(a[0]), "r"(a[1]), "r"(a[2]), "r"(a[3]), "r"(b[0]), "r"(b[1]));
}

// ============================================================
__global__ void k_nop() {}   // ncu launch-index shim

// ============================================================
// W -> W16T (fp16, transposed [c][k]) via 32x32 smem tiles
// ============================================================
__global__ __launch_bounds__(256) void k_cvtW(const float* __restrict__ W) {
    __shared__ float Ts[32][33];
    int k0 = blockIdx.y * 32, c0 = blockIdx.x * 32;
    int tx = threadIdx.x & 31, ty = threadIdx.x >> 5;
#pragma unroll
    for (int q = 0; q < 4; q++) {
        int r = ty + q * 8;
        Ts[r][tx] = W[(k0 + r) * CF + c0 + tx];
    }
    __syncthreads();
#pragma unroll
    for (int q = 0; q < 4; q++) {
        int cy = ty + q * 8;
        g_W16T[(c0 + cy) * KF + k0 + tx] = __float2half(Ts[tx][cy]);
    }
}

// ============================================================
// ws_t[hd][k] = sum_f W[k][h*64+f] * a[d*64+f]  (exact fp32)
// ============================================================
__global__ __launch_bounds__(256) void k_ws(const float* __restrict__ W,
                                            const float* __restrict__ a) {
    __shared__ float as[128];
    if (threadIdx.x < 128) as[threadIdx.x] = a[threadIdx.x];
    __syncthreads();
    int idx = blockIdx.x * 256 + threadIdx.x;     // 8192 total
    int hd = idx & 15, k = idx >> 4;
    int h = hd >> 1, d = hd & 1;
    const float* wr = W + k * CF + h * OF;
    const float* av = as + d * OF;
    float s = 0.f;
#pragma unroll 16
    for (int f = 0; f < OF; f++) s += wr[f] * av[f];
    g_wst[hd * KF + k] = s;
}

// ============================================================
// Whf16 = h @ W via HMMA (A: h fp32 converted on stage, B: W16T)
// CTA 128n x 64c, 8 warps (16 rows each)
// ============================================================
#define GASTR 72
#define GBSTR 72
__global__ __launch_bounds__(256) void k_gemm16(const float* __restrict__ h) {
    __shared__ __half As[128 * GASTR];
    __shared__ __half Bs[64 * GBSTR];
    int tid = threadIdx.x, wid = tid >> 5, lane = tid & 31;
    int n0 = blockIdx.y * 128, c0 = blockIdx.x * 64;
    float acc[8][4];
#pragma unroll
    for (int nt = 0; nt < 8; nt++)
#pragma unroll
        for (int q = 0; q < 4; q++) acc[nt][q] = 0.f;
    uint32_t aAddr = smem_u32(As) + (wid * 16 + (lane & 15)) * (GASTR * 2) + (lane >> 4) * 16;
    uint32_t bAddr = smem_u32(Bs) + (((lane & 7) + ((lane >> 4) & 1) * 8)) * (GBSTR * 2)
                   + ((lane >> 3) & 1) * 16;

    for (int k0 = 0; k0 < KF; k0 += 64) {
        __syncthreads();
#pragma unroll
        for (int q = 0; q < 8; q++) {
            int lin = tid + q * 256;
            int rr = lin >> 4, kq = (lin & 15) * 4;
            float4 v = *(const float4*)(h + (size_t)(n0 + rr) * KF + k0 + kq);
            *(__half2*)&As[rr * GASTR + kq]     = __floats2half2_rn(v.x, v.y);
            *(__half2*)&As[rr * GASTR + kq + 2] = __floats2half2_rn(v.z, v.w);
        }
#pragma unroll
        for (int q = 0; q < 2; q++) {
            int lin = tid + q * 256;
            int cc = lin >> 3, kq = (lin & 7) * 8;
            uint4 v = *(const uint4*)&g_W16T[(c0 + cc) * KF + k0 + kq];
            *(uint4*)&Bs[cc * GBSTR + kq] = v;
        }
        __syncthreads();
#pragma unroll
        for (int kc = 0; kc < 4; kc++) {
            uint32_t aa[4];
            ldsm4(aa[0], aa[1], aa[2], aa[3], aAddr + kc * 32);
            uint32_t b[16];
#pragma unroll
            for (int nq = 0; nq < 4; nq++)
                ldsm4(b[nq * 4], b[nq * 4 + 1], b[nq * 4 + 2], b[nq * 4 + 3],
                      bAddr + nq * 16 * (GBSTR * 2) + kc * 32);
#pragma unroll
            for (int nt = 0; nt < 8; nt++) mma16816(acc[nt], aa, &b[nt * 2]);
        }
    }
    int r0 = n0 + wid * 16 + (lane >> 2);
    int cb = c0 + (lane & 3) * 2;
#pragma unroll
    for (int nt = 0; nt < 8; nt++) {
        *(__half2*)&g_Whf16[(size_t)r0 * CF + cb + nt * 8] =
            __floats2half2_rn(acc[nt][0], acc[nt][1]);
        *(__half2*)&g_Whf16[(size_t)(r0 + 8) * CF + cb + nt * 8] =
            __floats2half2_rn(acc[nt][2], acc[nt][3]);
    }
}

// ============================================================
// PREP: pack adj bits; attrs via src/dst = h @ ws_t (fp32 exact);
// transpose Whf16 -> WhT (blocks 0..255)
// ============================================================
__global__ __launch_bounds__(256) void k_prep(const int* __restrict__ adj,
                                              const float* __restrict__ hsrc) {
    __shared__ __half Ts[64 * 130];
    int b = blockIdx.x, tid = threadIdx.x;
    int w = tid >> 5, lane = tid & 31;

#pragma unroll
    for (int q = 0; q < 16; q++) {
        int wd = w * 16 + q;
        int j = wd * 32 + lane;
        unsigned bt = __ballot_sync(0xFFFFFFFFu, adj[(size_t)b * NN + j] > 0);
        if (lane == 0) g_bits[b * 128 + wd] = bt;
    }

    {
        const float* hr  = hsrc + (size_t)b * KF;
        const float* wsS = g_wst + (2 * w) * KF;
        const float* wsD = g_wst + (2 * w + 1) * KF;
        float s = 0.f, d = 0.f;
#pragma unroll
        for (int t = 0; t < 16; t++) {
            float hv = hr[lane + 32 * t];
            s += hv * wsS[lane + 32 * t];
            d += hv * wsD[lane + 32 * t];
        }
#pragma unroll
        for (int o = 16; o; o >>= 1) {
            s += __shfl_xor_sync(0xFFFFFFFFu, s, o);
            d += __shfl_xor_sync(0xFFFFFFFFu, d, o);
        }
        if (lane == 0) {
            g_attrS[w * NN + b] = make_float4(s, expf(s) * 0.0625f, expf(0.2f * s) * 0.0625f, 0.f);
            __half* ap = (__half*)(g_attrP + w * (NN / 2) + (b >> 1)) + (b & 1);
            ap[0] = __float2half(d);
            ap[2] = __float2half(expf(d));
            ap[4] = __float2half(expf(0.2f * d));
        }
    }

    if (b < 256) {
        int hh = b & 7, n0 = (b >> 3) * 128;
#pragma unroll
        for (int q = 0; q < 32; q++) {
            int lin = tid + q * 256;
            int r = lin >> 6, c = lin & 63;
            Ts[c * 130 + r] = g_Whf16[(size_t)(n0 + r) * CF + hh * OF + c];
        }
        __syncthreads();
#pragma unroll
        for (int q = 0; q < 16; q++) {
            int lin = tid + q * 256;
            int f = lin >> 6, n2 = lin & 63;
            __half2 hv = __halves2half2(Ts[f * 130 + n2 * 2], Ts[f * 130 + n2 * 2 + 1]);
            *(__half2*)&g_WhT[(hh * OF + f) * NN + n0 + n2 * 2] = hv;
        }
    }
}

// ============================================================
// GAT: register-A-fragment score gen, 4x2 warp grid, B-only smem
// ============================================================
#define BSTR 72
#define BBUF 9216                       // 64*72*2
#define SM_TOT (2 * BBUF + 512)

__global__ __launch_bounds__(256, 2) void k_gat_mma(float* __restrict__ out) {
    extern __shared__ char sm[];
    uint32_t sb = smem_u32(sm);
    float* zsm = (float*)(sm + 2 * BBUF);

    int tid = threadIdx.x, wid = tid >> 5, lane = tid & 31;
    int head = blockIdx.x, i0 = blockIdx.y << 7;
    int wm = wid & 3, wn = wid >> 2;     // rows wm*32, cols wn*32
    int r = lane >> 2, t = lane & 3;

    // i-attrs for the 4 rows this lane owns (r, r+8, r+16, r+24)
    __half2 isrc[4], ies[4], ies2[4];
    const unsigned* bitp[4];
#pragma unroll
    for (int q = 0; q < 4; q++) {
        int row = i0 + wm * 32 + r + q * 8;
        float4 v = g_attrS[head * NN + row];
        isrc[q] = __float2half2_rn(v.x);
        ies[q]  = __float2half2_rn(v.y);
        ies2[q] = __float2half2_rn(v.z);
        bitp[q] = g_bits + (size_t)row * 128;
    }
    const uint4* jp = g_attrP + head * (NN / 2);

    float acc[2][4][4], accz[2][4];
#pragma unroll
    for (int mt = 0; mt < 2; mt++) {
#pragma unroll
        for (int nt = 0; nt < 4; nt++)
#pragma unroll
            for (int q = 0; q < 4; q++) acc[mt][nt][q] = 0.f;
#pragma unroll
        for (int q = 0; q < 4; q++) accz[mt][q] = 0.f;
    }
    uint32_t bz[2];
    bz[0] = bz[1] = (lane < 4) ? 0x3C003C00u : 0u;

    // B ldmatrix address (this warp's 32-col half)
    uint32_t bAddr = sb + (wn * 32 + (lane & 7) + ((lane >> 4) & 1) * 8) * (BSTR * 2)
                   + ((lane >> 3) & 1) * 16;

    auto stageB = [&](int j0, int bufn) {
        __half* Bd = (__half*)(sm + bufn * BBUF);
#pragma unroll
        for (int q = 0; q < 2; q++) {
            int lin = tid + q * 256;
            int f = lin >> 3, c = lin & 7;
            uint4 v = *(const uint4*)&g_WhT[(head * OF + f) * NN + j0 + c * 8];
            *(uint4*)&Bd[f * BSTR + c * 8] = v;
        }
    };

    stageB(0, 0);
    const __half2 z2h = __float2half2_rn(0.f);

    for (int s = 0; s < 64; s++) {
        int buf = s & 1;
        __syncthreads();
        if (s < 63) stageB((s + 1) << 6, buf ^ 1);

        uint2 mw[4];
#pragma unroll
        for (int q = 0; q < 4; q++)
            mw[q] = *(const uint2*)(bitp[q] + s * 2);

#pragma unroll
        for (int kc = 0; kc < 4; kc++) {
            uint4 JA = jp[s * 32 + kc * 8 + t];
            uint4 JB = jp[s * 32 + kc * 8 + 4 + t];
            __half2 dA  = *(__half2*)&JA.x, eA  = *(__half2*)&JA.y, e2A = *(__half2*)&JA.z;
            __half2 dB  = *(__half2*)&JB.x, eB  = *(__half2*)&JB.y, e2B = *(__half2*)&JB.z;
            int sh = ((kc & 1) * 8 + t) * 2;
            uint32_t amt[2][4];
#pragma unroll
            for (int q = 0; q < 4; q++) {
                unsigned wd = (kc & 2) ? mw[q].y : mw[q].x;
                unsigned bA = (wd >> sh) & 3u;
                unsigned bB = (wd >> (sh + 8)) & 3u;
                unsigned mA = ((bA & 1u) ? 0x0000FFFFu : 0u) | ((bA & 2u) ? 0xFFFF0000u : 0u);
                unsigned mB = ((bB & 1u) ? 0x0000FFFFu : 0u) | ((bB & 2u) ? 0xFFFF0000u : 0u);
                unsigned gA = __hgt2_mask(__hadd2(isrc[q], dA), z2h);
                unsigned gB = __hgt2_mask(__hadd2(isrc[q], dB), z2h);
                unsigned vA = ((h2u(__hmul2(ies[q], eA)) & gA) |
                               (h2u(__hmul2(ies2[q], e2A)) & ~gA)) & mA;
                unsigned vB = ((h2u(__hmul2(ies[q], eB)) & gB) |
                               (h2u(__hmul2(ies2[q], e2B)) & ~gB)) & mB;
                amt[q >> 1][q & 1]       = vA;   // a0/a1 (rows r, r+8 of m-tile)
                amt[q >> 1][(q & 1) + 2] = vB;   // a2/a3
            }
            uint32_t b[8];
#pragma unroll
            for (int nq = 0; nq < 2; nq++)
                ldsm4(b[nq * 4], b[nq * 4 + 1], b[nq * 4 + 2], b[nq * 4 + 3],
                      bAddr + buf * BBUF + nq * 16 * (BSTR * 2) + kc * 32);
#pragma unroll
            for (int mt = 0; mt < 2; mt++) {
#pragma unroll
                for (int nq = 0; nq < 2; nq++) {
                    mma16816(acc[mt][nq * 2],     amt[mt], &b[nq * 4]);
                    mma16816(acc[mt][nq * 2 + 1], amt[mt], &b[nq * 4 + 2]);
                }
                if (wn == 0) mma16816(accz[mt], amt[mt], bz);
            }
        }
    }

    // publish Z (wn==0 warps, lanes t==0 hold col 0)
    if (wn == 0 && t == 0) {
        int rb = wm * 32 + r;
        zsm[rb]      = accz[0][0];
        zsm[rb + 8]  = accz[0][2];
        zsm[rb + 16] = accz[1][0];
        zsm[rb + 24] = accz[1][2];
    }
    __syncthreads();

    int rloc = wm * 32 + r;
    float inv0 = 1.0f / zsm[rloc];
    float inv1 = 1.0f / zsm[rloc + 8];
    float inv2 = 1.0f / zsm[rloc + 16];
    float inv3 = 1.0f / zsm[rloc + 24];
    int cb = head * OF + wn * 32 + t * 2;
#pragma unroll
    for (int mt = 0; mt < 2; mt++) {
        float iv0 = mt ? inv2 : inv0;
        float iv1 = mt ? inv3 : inv1;
        int row0 = i0 + rloc + mt * 16;
#pragma unroll
        for (int nt = 0; nt < 4; nt++) {
            float v0 = acc[mt][nt][0] * iv0, v1 = acc[mt][nt][1] * iv0;
            float v2 = acc[mt][nt][2] * iv1, v3 = acc[mt][nt][3] * iv1;
            v0 = v0 > 0.f ? v0 : (expf(v0) - 1.0f);
            v1 = v1 > 0.f ? v1 : (expf(v1) - 1.0f);
            v2 = v2 > 0.f ? v2 : (expf(v2) - 1.0f);
            v3 = v3 > 0.f ? v3 : (expf(v3) - 1.0f);
            *(float2*)(out + (size_t)row0 * CF + cb + nt * 8)       = make_float2(v0, v1);
            *(float2*)(out + (size_t)(row0 + 8) * CF + cb + nt * 8) = make_float2(v2, v3);
        }
    }
}

// ============================================================
extern "C" void kernel_launch(void* const* d_in, const int* in_sizes, int n_in,
                              void* d_out, int out_size) {
    const float* h   = (const float*)d_in[0];
    const int*   adj = (const int*)d_in[1];
    const float* W   = (const float*)d_in[2];
    const float* a   = (const float*)d_in[3];
    float* out = (float*)d_out;

    k_nop<<<1, 32>>>();
    k_cvtW<<<dim3(16, 16), 256>>>(W);
    k_ws<<<32, 256>>>(W, a);
    k_gemm16<<<dim3(8, 32), 256>>>(h);
    k_prep<<<NN, 256>>>(adj, h);

    cudaFuncSetAttribute(k_gat_mma, cudaFuncAttributeMaxDynamicSharedMemorySize, SM_TOT);
    k_gat_mma<<<dim3(NH, NN / 128), 256, SM_TOT>>>(out);
}

// round 10
// speedup vs baseline: 1.5868x; 1.5868x over previous
#include <cuda_runtime.h>
#include <cuda_fp16.h>
#include <math.h>
#include <stdint.h>

#define NN   4096
#define KF   512     // IN_F
#define CF   512     // OUT_F * N_HEADS
#define NH   8
#define OF   64

// ---- scratch (device globals; no allocation allowed) ----
__device__ __half   g_W16T[CF * KF];          // 512 KB  W fp16 transposed [c][k]
__device__ float    g_wst[16 * KF];           // 32 KB   ws_t[h*2+d][k]
__device__ __half   g_Whf16[(size_t)NN * CF]; // 4 MB    Wh fp16 [n][c]
__device__ __half   g_WhT[NH * OF * NN];      // 4 MB    values transposed [h][f][n]
__device__ float4   g_attrS[NH * NN];         // (src, Es/16, Es2/16, 0)
__device__ uint4    g_attrP[NH * (NN / 2)];   // per j-pair: (dst2, Ed2, Ed22, pad)
__device__ unsigned g_amask[(size_t)NN * (NN / 2)];  // 32 MB expanded masks

__device__ __forceinline__ uint32_t smem_u32(const void* p) {
    uint32_t a;
    asm("{ .reg .u64 t; cvta.to.shared.u64 t, %1; cvt.u32.u64 %0, t; }" : "=r"(a) : "l"(p));
    return a;
}
__device__ __forceinline__ unsigned h2u(__half2 v) {
    return *reinterpret_cast<unsigned*>(&v);
}
__device__ __forceinline__ void ldsm4(uint32_t& r0, uint32_t& r1, uint32_t& r2, uint32_t& r3,
                                      uint32_t addr) {
    asm volatile("ldmatrix.sync.aligned.m8n8.x4.shared.b16 {%0,%1,%2,%3}, [%4];"
                 : "=r"(r0), "=r"(r1), "=r"(r2), "=r"(r3) : "r"(addr));
}
__device__ __forceinline__ void mma16816(float* d, const uint32_t* a, const uint32_t* b) {
    asm volatile(
        "mma.sync.aligned.m16n8k16.row.col.f32.f16.f16.f32 "
        "{%0,%1,%2,%3}, {%4,%5,%6,%7}, {%8,%9}, {%0,%1,%2,%3};"
        : "+f"(d[0]), "+f"(d[1]), "+f"(d[2]), "+f"(d[3])
        : "r"(a[0]), "r"(a[1]), "r"(a[2]), "r"(a[3]), "r"(b[0]), "r"(b[1]));
}

// ============================================================
__global__ void k_nop() {}   // ncu launch-index shim

// ============================================================
// W -> W16T (fp16, transposed [c][k])
// ============================================================
__global__ __launch_bounds__(256) void k_cvtW(const float* __restrict__ W) {
    __shared__ float Ts[32][33];
    int k0 = blockIdx.y * 32, c0 = blockIdx.x * 32;
    int tx = threadIdx.x & 31, ty = threadIdx.x >> 5;
#pragma unroll
    for (int q = 0; q < 4; q++) {
        int r = ty + q * 8;
        Ts[r][tx] = W[(k0 + r) * CF + c0 + tx];
    }
    __syncthreads();
#pragma unroll
    for (int q = 0; q < 4; q++) {
        int cy = ty + q * 8;
        g_W16T[(c0 + cy) * KF + k0 + tx] = __float2half(Ts[tx][cy]);
    }
}

// ============================================================
// ws_t[hd][k] = sum_f W[k][h*64+f] * a[d*64+f]  (exact fp32)
// ============================================================
__global__ __launch_bounds__(256) void k_ws(const float* __restrict__ W,
                                            const float* __restrict__ a) {
    __shared__ float as[128];
    if (threadIdx.x < 128) as[threadIdx.x] = a[threadIdx.x];
    __syncthreads();
    int idx = blockIdx.x * 256 + threadIdx.x;
    int hd = idx & 15, k = idx >> 4;
    int h = hd >> 1, d = hd & 1;
    const float* wr = W + k * CF + h * OF;
    const float* av = as + d * OF;
    float s = 0.f;
#pragma unroll 16
    for (int f = 0; f < OF; f++) s += wr[f] * av[f];
    g_wst[hd * KF + k] = s;
}

// ============================================================
// Whf16 = h @ W via HMMA
// ============================================================
#define GASTR 72
#define GBSTR 72
__global__ __launch_bounds__(256) void k_gemm16(const float* __restrict__ h) {
    __shared__ __half As[128 * GASTR];
    __shared__ __half Bs[64 * GBSTR];
    int tid = threadIdx.x, wid = tid >> 5, lane = tid & 31;
    int n0 = blockIdx.y * 128, c0 = blockIdx.x * 64;
    float acc[8][4];
#pragma unroll
    for (int nt = 0; nt < 8; nt++)
#pragma unroll
        for (int q = 0; q < 4; q++) acc[nt][q] = 0.f;
    uint32_t aAddr = smem_u32(As) + (wid * 16 + (lane & 15)) * (GASTR * 2) + (lane >> 4) * 16;
    uint32_t bAddr = smem_u32(Bs) + (((lane & 7) + ((lane >> 4) & 1) * 8)) * (GBSTR * 2)
                   + ((lane >> 3) & 1) * 16;

    for (int k0 = 0; k0 < KF; k0 += 64) {
        __syncthreads();
#pragma unroll
        for (int q = 0; q < 8; q++) {
            int lin = tid + q * 256;
            int rr = lin >> 4, kq = (lin & 15) * 4;
            float4 v = *(const float4*)(h + (size_t)(n0 + rr) * KF + k0 + kq);
            *(__half2*)&As[rr * GASTR + kq]     = __floats2half2_rn(v.x, v.y);
            *(__half2*)&As[rr * GASTR + kq + 2] = __floats2half2_rn(v.z, v.w);
        }
#pragma unroll
        for (int q = 0; q < 2; q++) {
            int lin = tid + q * 256;
            int cc = lin >> 3, kq = (lin & 7) * 8;
            uint4 v = *(const uint4*)&g_W16T[(c0 + cc) * KF + k0 + kq];
            *(uint4*)&Bs[cc * GBSTR + kq] = v;
        }
        __syncthreads();
#pragma unroll
        for (int kc = 0; kc < 4; kc++) {
            uint32_t aa[4];
            ldsm4(aa[0], aa[1], aa[2], aa[3], aAddr + kc * 32);
            uint32_t b[16];
#pragma unroll
            for (int nq = 0; nq < 4; nq++)
                ldsm4(b[nq * 4], b[nq * 4 + 1], b[nq * 4 + 2], b[nq * 4 + 3],
                      bAddr + nq * 16 * (GBSTR * 2) + kc * 32);
#pragma unroll
            for (int nt = 0; nt < 8; nt++) mma16816(acc[nt], aa, &b[nt * 2]);
        }
    }
    int r0 = n0 + wid * 16 + (lane >> 2);
    int cb = c0 + (lane & 3) * 2;
#pragma unroll
    for (int nt = 0; nt < 8; nt++) {
        *(__half2*)&g_Whf16[(size_t)r0 * CF + cb + nt * 8] =
            __floats2half2_rn(acc[nt][0], acc[nt][1]);
        *(__half2*)&g_Whf16[(size_t)(r0 + 8) * CF + cb + nt * 8] =
            __floats2half2_rn(acc[nt][2], acc[nt][3]);
    }
}

// ============================================================
// PREP: pack+expand adj masks; attrs via h @ ws_t (exact);
// transpose Whf16 -> WhT (blocks 0..255)
// ============================================================
__global__ __launch_bounds__(256) void k_prep(const int* __restrict__ adj,
                                              const float* __restrict__ hsrc) {
    __shared__ __half Ts[64 * 130];
    __shared__ unsigned sbits[128];
    int b = blockIdx.x, tid = threadIdx.x;
    int w = tid >> 5, lane = tid & 31;

    // pack adj row b into smem words
#pragma unroll
    for (int q = 0; q < 16; q++) {
        int wd = w * 16 + q;
        int j = wd * 32 + lane;
        unsigned bt = __ballot_sync(0xFFFFFFFFu, adj[(size_t)b * NN + j] > 0);
        if (lane == 0) sbits[wd] = bt;
    }

    // attrs: (node b, head w), exact fp32 via ws_t
    {
        const float* hr  = hsrc + (size_t)b * KF;
        const float* wsS = g_wst + (2 * w) * KF;
        const float* wsD = g_wst + (2 * w + 1) * KF;
        float s = 0.f, d = 0.f;
#pragma unroll
        for (int t = 0; t < 16; t++) {
            float hv = hr[lane + 32 * t];
            s += hv * wsS[lane + 32 * t];
            d += hv * wsD[lane + 32 * t];
        }
#pragma unroll
        for (int o = 16; o; o >>= 1) {
            s += __shfl_xor_sync(0xFFFFFFFFu, s, o);
            d += __shfl_xor_sync(0xFFFFFFFFu, d, o);
        }
        if (lane == 0) {
            g_attrS[w * NN + b] = make_float4(s, expf(s) * 0.0625f, expf(0.2f * s) * 0.0625f, 0.f);
            __half* ap = (__half*)(g_attrP + w * (NN / 2) + (b >> 1)) + (b & 1);
            ap[0] = __float2half(d);
            ap[2] = __float2half(expf(d));
            ap[4] = __float2half(expf(0.2f * d));
        }
    }
    __syncthreads();

    // expand adjacency bits to per-pair 32-bit masks
#pragma unroll
    for (int q = 0; q < 8; q++) {
        int p = tid + q * 256;
        unsigned sel = (sbits[p >> 4] >> ((p & 15) * 2)) & 3u;
        unsigned m = ((sel & 1u) ? 0x0000FFFFu : 0u) | ((sel & 2u) ? 0xFFFF0000u : 0u);
        g_amask[(size_t)b * (NN / 2) + p] = m;
    }

    // transpose (blocks 0..255): head = b&7, rows [(b>>3)*128, +128)
    if (b < 256) {
        int hh = b & 7, n0 = (b >> 3) * 128;
#pragma unroll
        for (int q = 0; q < 32; q++) {
            int lin = tid + q * 256;
            int r = lin >> 6, c = lin & 63;
            Ts[c * 130 + r] = g_Whf16[(size_t)(n0 + r) * CF + hh * OF + c];
        }
        __syncthreads();
#pragma unroll
        for (int q = 0; q < 16; q++) {
            int lin = tid + q * 256;
            int f = lin >> 6, n2 = lin & 63;
            __half2 hv = __halves2half2(Ts[f * 130 + n2 * 2], Ts[f * 130 + n2 * 2 + 1]);
            *(__half2*)&g_WhT[(hh * OF + f) * NN + n0 + n2 * 2] = hv;
        }
    }
}

// ============================================================
// Kernel C (R8-measured version): fused attention, HMMA pipeline,
// half2 score generation into smem S, double-buffered
// ============================================================
#define SSTR 72
#define BSTR 72
#define SBUF 18432
#define BBUF 9216
#define SM_S    0
#define SM_B    36864
#define SM_TOT  55296

__global__ __launch_bounds__(256, 2) void k_gat_mma(float* __restrict__ out) {
    extern __shared__ char sm[];
    uint32_t sb = smem_u32(sm);

    int tid = threadIdx.x, wid = tid >> 5, lane = tid & 31;
    int head = blockIdx.x, i0 = blockIdx.y << 7;

    int jg = tid & 7, quad = tid >> 3;
    __half2 src2[4], es2[4], es22[4];
#pragma unroll
    for (int r = 0; r < 4; r++) {
        float4 v = g_attrS[head * NN + i0 + quad * 4 + r];
        src2[r] = __float2half2_rn(v.x);
        es2[r]  = __float2half2_rn(v.y);
        es22[r] = __float2half2_rn(v.z);
    }
    const uint4* attrP = g_attrP + head * (NN / 2);
    const unsigned* amrow = g_amask + (size_t)(i0 + quad * 4) * (NN / 2);

    float acc[8][4], accz[4];
#pragma unroll
    for (int nt = 0; nt < 8; nt++)
#pragma unroll
        for (int q = 0; q < 4; q++) acc[nt][q] = 0.f;
#pragma unroll
    for (int q = 0; q < 4; q++) accz[q] = 0.f;

    uint32_t bz[2];
    bz[0] = bz[1] = (lane < 4) ? 0x3C003C00u : 0u;

    uint32_t aA[2], bA[2];
    {
        uint32_t aoff = (wid * 16 + (lane & 15)) * (SSTR * 2) + (lane >> 4) * 16;
        uint32_t boff = (((lane & 7) + ((lane >> 4) & 1) * 8)) * (BSTR * 2)
                      + ((lane >> 3) & 1) * 16;
        aA[0] = sb + SM_S + aoff;          aA[1] = aA[0] + SBUF;
        bA[0] = sb + SM_B + boff;          bA[1] = bA[0] + BBUF;
    }

    auto stageB = [&](int j0, int bufn) {
        __half* Bd = (__half*)(sm + SM_B + bufn * BBUF);
#pragma unroll
        for (int q = 0; q < 2; q++) {
            int lin = tid + q * 256;
            int f = lin >> 3, c = lin & 7;
            uint4 v = *(const uint4*)&g_WhT[(head * OF + f) * NN + j0 + c * 8];
            *(uint4*)&Bd[f * BSTR + c * 8] = v;
        }
    };

    auto genS = [&](int j0, int bufn) {
        uint32_t* Sd = (uint32_t*)((__half*)(sm + SM_S + bufn * SBUF)
                                   + (quad * 4) * SSTR + jg * 8);
        int pb = (j0 >> 1) + jg * 4;
        const uint4* jp = attrP + pb;
        uint4 am0 = *(const uint4*)(amrow + pb);
        uint4 am1 = *(const uint4*)(amrow + (NN / 2) + pb);
        uint4 am2 = *(const uint4*)(amrow + 2 * (NN / 2) + pb);
        uint4 am3 = *(const uint4*)(amrow + 3 * (NN / 2) + pb);
        const __half2 zero2 = __float2half2_rn(0.f);
#pragma unroll
        for (int k = 0; k < 4; k++) {
            uint4 J = jp[k];
            __half2 dst2  = *(__half2*)&J.x;
            __half2 ed2   = *(__half2*)&J.y;
            __half2 ed22  = *(__half2*)&J.z;
            unsigned amk[4] = {
                (&am0.x)[k], (&am1.x)[k], (&am2.x)[k], (&am3.x)[k]
            };
#pragma unroll
            for (int r = 0; r < 4; r++) {
                __half2 t = __hadd2(src2[r], dst2);
                unsigned m = __hgt2_mask(t, zero2);
                unsigned pa = h2u(__hmul2(es2[r], ed2));
                unsigned pbv = h2u(__hmul2(es22[r], ed22));
                unsigned p = ((pa & m) | (pbv & ~m)) & amk[r];
                Sd[r * (SSTR / 2) + k] = p;
            }
        }
    };

    stageB(0, 0);
    genS(0, 0);

    for (int s = 0; s < 64; s++) {
        int buf = s & 1;
        __syncthreads();
        if (s < 63) stageB((s + 1) << 6, buf ^ 1);

#pragma unroll
        for (int kc = 0; kc < 4; kc++) {
            uint32_t a[4];
            ldsm4(a[0], a[1], a[2], a[3], aA[buf] + kc * 32);
            uint32_t b[16];
#pragma unroll
            for (int nq = 0; nq < 4; nq++)
                ldsm4(b[nq * 4], b[nq * 4 + 1], b[nq * 4 + 2], b[nq * 4 + 3],
                      bA[buf] + nq * 16 * (BSTR * 2) + kc * 32);
#pragma unroll
            for (int nt = 0; nt < 8; nt++)
                mma16816(acc[nt], a, &b[nt * 2]);
            mma16816(accz, a, bz);
        }

        if (s < 63) genS((s + 1) << 6, buf ^ 1);
    }

    float z0 = __shfl_sync(0xFFFFFFFFu, accz[0], lane & 28);
    float z1 = __shfl_sync(0xFFFFFFFFu, accz[2], lane & 28);
    float inv0 = 1.0f / z0;
    float inv1 = 1.0f / z1;

    {
        int r0 = wid * 16 + (lane >> 2);
        float* o0 = out + (size_t)(i0 + r0) * CF + head * OF + (lane & 3) * 2;
        float* o1 = o0 + 8 * CF;
#pragma unroll
        for (int nt = 0; nt < 8; nt++) {
            float v0 = acc[nt][0] * inv0, v1 = acc[nt][1] * inv0;
            float v2 = acc[nt][2] * inv1, v3 = acc[nt][3] * inv1;
            v0 = v0 > 0.f ? v0 : (expf(v0) - 1.0f);
            v1 = v1 > 0.f ? v1 : (expf(v1) - 1.0f);
            v2 = v2 > 0.f ? v2 : (expf(v2) - 1.0f);
            v3 = v3 > 0.f ? v3 : (expf(v3) - 1.0f);
            *(float2*)(o0 + nt * 8) = make_float2(v0, v1);
            *(float2*)(o1 + nt * 8) = make_float2(v2, v3);
        }
    }
}

// ============================================================
extern "C" void kernel_launch(void* const* d_in, const int* in_sizes, int n_in,
                              void* d_out, int out_size) {
    const float* h   = (const float*)d_in[0];
    const int*   adj = (const int*)d_in[1];
    const float* W   = (const float*)d_in[2];
    const float* a   = (const float*)d_in[3];
    float* out = (float*)d_out;

    k_nop<<<1, 32>>>();
    k_cvtW<<<dim3(16, 16), 256>>>(W);
    k_ws<<<32, 256>>>(W, a);
    k_gemm16<<<dim3(8, 32), 256>>>(h);
    k_prep<<<NN, 256>>>(adj, h);

    cudaFuncSetAttribute(k_gat_mma, cudaFuncAttributeMaxDynamicSharedMemorySize, SM_TOT);
    k_gat_mma<<<dim3(NH, NN / 128), 256, SM_TOT>>>(out);
}

// round 11
// speedup vs baseline: 1.7039x; 1.0738x over previous
#include <cuda_runtime.h>
#include <cuda_fp16.h>
#include <math.h>
#include <stdint.h>

#define NN   4096
#define KF   512     // IN_F
#define CF   512     // OUT_F * N_HEADS
#define NH   8
#define OF   64

// ---- scratch (device globals; no allocation allowed) ----
__device__ __half   g_W16T[CF * KF];          // 512 KB  W fp16 transposed [c][k]
__device__ float    g_wst[16 * KF];           // 32 KB   ws_t[h*2+d][k]
__device__ __half   g_Whf16[(size_t)NN * CF]; // 4 MB    Wh fp16 [n][c]
__device__ __half   g_WhT[NH * OF * NN];      // 4 MB    values transposed [h][f][n]
__device__ unsigned g_bits[NN * 128];         // 2 MB    packed adj
__device__ float4   g_attrS[NH * NN];         // (src, Es/16, Es2/16, 0)
__device__ uint4    g_attrP[NH * (NN / 2)];   // per j-pair: (dst2, Ed2, Ed22, pad)

__device__ __forceinline__ uint32_t smem_u32(const void* p) {
    uint32_t a;
    asm("{ .reg .u64 t; cvta.to.shared.u64 t, %1; cvt.u32.u64 %0, t; }" : "=r"(a) : "l"(p));
    return a;
}
__device__ __forceinline__ unsigned h2u(__half2 v) {
    return *reinterpret_cast<unsigned*>(&v);
}
__device__ __forceinline__ void ldsm4(uint32_t& r0, uint32_t& r1, uint32_t& r2, uint32_t& r3,
                                      uint32_t addr) {
    asm volatile("ldmatrix.sync.aligned.m8n8.x4.shared.b16 {%0,%1,%2,%3}, [%4];"
                 : "=r"(r0), "=r"(r1), "=r"(r2), "=r"(r3) : "r"(addr));
}
__device__ __forceinline__ void mma16816(float* d, const uint32_t* a, const uint32_t* b) {
    asm volatile(
        "mma.sync.aligned.m16n8k16.row.col.f32.f16.f16.f32 "
        "{%0,%1,%2,%3}, {%4,%5,%6,%7}, {%8,%9}, {%0,%1,%2,%3};"
        : "+f"(d[0]), "+f"(d[1]), "+f"(d[2]), "+f"(d[3])
        : "r"(a[0]), "r"(a[1]), "r"(a[2]), "r"(a[3]), "r"(b[0]), "r"(b[1]));
}

// ============================================================
__global__ void k_nop() {}   // ncu launch-index shim

// ============================================================
// W -> W16T (fp16, transposed [c][k])
// ============================================================
__global__ __launch_bounds__(256) void k_cvtW(const float* __restrict__ W) {
    __shared__ float Ts[32][33];
    int k0 = blockIdx.y * 32, c0 = blockIdx.x * 32;
    int tx = threadIdx.x & 31, ty = threadIdx.x >> 5;
#pragma unroll
    for (int q = 0; q < 4; q++) {
        int r = ty + q * 8;
        Ts[r][tx] = W[(k0 + r) * CF + c0 + tx];
    }
    __syncthreads();
#pragma unroll
    for (int q = 0; q < 4; q++) {
        int cy = ty + q * 8;
        g_W16T[(c0 + cy) * KF + k0 + tx] = __float2half(Ts[tx][cy]);
    }
}

// ============================================================
// ws_t[hd][k] = sum_f W[k][h*64+f] * a[d*64+f]  (exact fp32)
// ============================================================
__global__ __launch_bounds__(256) void k_ws(const float* __restrict__ W,
                                            const float* __restrict__ a) {
    __shared__ float as[128];
    if (threadIdx.x < 128) as[threadIdx.x] = a[threadIdx.x];
    __syncthreads();
    int idx = blockIdx.x * 256 + threadIdx.x;
    int hd = idx & 15, k = idx >> 4;
    int h = hd >> 1, d = hd & 1;
    const float* wr = W + k * CF + h * OF;
    const float* av = as + d * OF;
    float s = 0.f;
#pragma unroll 16
    for (int f = 0; f < OF; f++) s += wr[f] * av[f];
    g_wst[hd * KF + k] = s;
}

// ============================================================
// Whf16 = h @ W via HMMA
// ============================================================
#define GASTR 72
#define GBSTR 72
__global__ __launch_bounds__(256) void k_gemm16(const float* __restrict__ h) {
    __shared__ __half As[128 * GASTR];
    __shared__ __half Bs[64 * GBSTR];
    int tid = threadIdx.x, wid = tid >> 5, lane = tid & 31;
    int n0 = blockIdx.y * 128, c0 = blockIdx.x * 64;
    float acc[8][4];
#pragma unroll
    for (int nt = 0; nt < 8; nt++)
#pragma unroll
        for (int q = 0; q < 4; q++) acc[nt][q] = 0.f;
    uint32_t aAddr = smem_u32(As) + (wid * 16 + (lane & 15)) * (GASTR * 2) + (lane >> 4) * 16;
    uint32_t bAddr = smem_u32(Bs) + (((lane & 7) + ((lane >> 4) & 1) * 8)) * (GBSTR * 2)
                   + ((lane >> 3) & 1) * 16;

    for (int k0 = 0; k0 < KF; k0 += 64) {
        __syncthreads();
#pragma unroll
        for (int q = 0; q < 8; q++) {
            int lin = tid + q * 256;
            int rr = lin >> 4, kq = (lin & 15) * 4;
            float4 v = *(const float4*)(h + (size_t)(n0 + rr) * KF + k0 + kq);
            *(__half2*)&As[rr * GASTR + kq]     = __floats2half2_rn(v.x, v.y);
            *(__half2*)&As[rr * GASTR + kq + 2] = __floats2half2_rn(v.z, v.w);
        }
#pragma unroll
        for (int q = 0; q < 2; q++) {
            int lin = tid + q * 256;
            int cc = lin >> 3, kq = (lin & 7) * 8;
            uint4 v = *(const uint4*)&g_W16T[(c0 + cc) * KF + k0 + kq];
            *(uint4*)&Bs[cc * GBSTR + kq] = v;
        }
        __syncthreads();
#pragma unroll
        for (int kc = 0; kc < 4; kc++) {
            uint32_t aa[4];
            ldsm4(aa[0], aa[1], aa[2], aa[3], aAddr + kc * 32);
            uint32_t b[16];
#pragma unroll
            for (int nq = 0; nq < 4; nq++)
                ldsm4(b[nq * 4], b[nq * 4 + 1], b[nq * 4 + 2], b[nq * 4 + 3],
                      bAddr + nq * 16 * (GBSTR * 2) + kc * 32);
#pragma unroll
            for (int nt = 0; nt < 8; nt++) mma16816(acc[nt], aa, &b[nt * 2]);
        }
    }
    int r0 = n0 + wid * 16 + (lane >> 2);
    int cb = c0 + (lane & 3) * 2;
#pragma unroll
    for (int nt = 0; nt < 8; nt++) {
        *(__half2*)&g_Whf16[(size_t)r0 * CF + cb + nt * 8] =
            __floats2half2_rn(acc[nt][0], acc[nt][1]);
        *(__half2*)&g_Whf16[(size_t)(r0 + 8) * CF + cb + nt * 8] =
            __floats2half2_rn(acc[nt][2], acc[nt][3]);
    }
}

// ============================================================
// PREP: pack adj bits; attrs via h @ ws_t (exact);
// transpose Whf16 -> WhT (blocks 0..255)
// ============================================================
__global__ __launch_bounds__(256) void k_prep(const int* __restrict__ adj,
                                              const float* __restrict__ hsrc) {
    __shared__ __half Ts[64 * 130];
    int b = blockIdx.x, tid = threadIdx.x;
    int w = tid >> 5, lane = tid & 31;

    // pack adj row b
#pragma unroll
    for (int q = 0; q < 16; q++) {
        int wd = w * 16 + q;
        int j = wd * 32 + lane;
        unsigned bt = __ballot_sync(0xFFFFFFFFu, adj[(size_t)b * NN + j] > 0);
        if (lane == 0) g_bits[b * 128 + wd] = bt;
    }

    // attrs: (node b, head w), exact fp32 via ws_t
    {
        const float* hr  = hsrc + (size_t)b * KF;
        const float* wsS = g_wst + (2 * w) * KF;
        const float* wsD = g_wst + (2 * w + 1) * KF;
        float s = 0.f, d = 0.f;
#pragma unroll
        for (int t = 0; t < 16; t++) {
            float hv = hr[lane + 32 * t];
            s += hv * wsS[lane + 32 * t];
            d += hv * wsD[lane + 32 * t];
        }
#pragma unroll
        for (int o = 16; o; o >>= 1) {
            s += __shfl_xor_sync(0xFFFFFFFFu, s, o);
            d += __shfl_xor_sync(0xFFFFFFFFu, d, o);
        }
        if (lane == 0) {
            g_attrS[w * NN + b] = make_float4(s, expf(s) * 0.0625f, expf(0.2f * s) * 0.0625f, 0.f);
            __half* ap = (__half*)(g_attrP + w * (NN / 2) + (b >> 1)) + (b & 1);
            ap[0] = __float2half(d);
            ap[2] = __float2half(expf(d));
            ap[4] = __float2half(expf(0.2f * d));
        }
    }

    // transpose (blocks 0..255)
    if (b < 256) {
        int hh = b & 7, n0 = (b >> 3) * 128;
        __syncthreads();
#pragma unroll
        for (int q = 0; q < 32; q++) {
            int lin = tid + q * 256;
            int r = lin >> 6, c = lin & 63;
            Ts[c * 130 + r] = g_Whf16[(size_t)(n0 + r) * CF + hh * OF + c];
        }
        __syncthreads();
#pragma unroll
        for (int q = 0; q < 16; q++) {
            int lin = tid + q * 256;
            int f = lin >> 6, n2 = lin & 63;
            __half2 hv = __halves2half2(Ts[f * 130 + n2 * 2], Ts[f * 130 + n2 * 2 + 1]);
            *(__half2*)&g_WhT[(hh * OF + f) * NN + n0 + n2 * 2] = hv;
        }
    }
}

// ============================================================
// GAT: A-fragments generated in registers (double-buffered),
// B-only smem (double-buffered), 8 warps x 16 rows x 64 cols
// ============================================================
#define BSTR 72
#define BBUF 9216                       // 64*72*2
#define SM_TOT (2 * BBUF + 128)

__global__ __launch_bounds__(256, 2) void k_gat_mma(float* __restrict__ out) {
    extern __shared__ char sm[];
    uint32_t sb = smem_u32(sm);

    int tid = threadIdx.x, wid = tid >> 5, lane = tid & 31;
    int head = blockIdx.x, i0 = blockIdx.y << 7;
    int r = lane >> 2, t = lane & 3;
    int t2 = t << 1;

    // this lane's two rows: r and r+8 within the warp's 16-row band
    int row0 = i0 + wid * 16 + r;
    __half2 isrc[2], ies[2], ies2[2];
    {
        float4 v0 = g_attrS[head * NN + row0];
        float4 v1 = g_attrS[head * NN + row0 + 8];
        isrc[0] = __float2half2_rn(v0.x); ies[0] = __float2half2_rn(v0.y);
        ies2[0] = __float2half2_rn(v0.z);
        isrc[1] = __float2half2_rn(v1.x); ies[1] = __float2half2_rn(v1.y);
        ies2[1] = __float2half2_rn(v1.z);
    }
    const unsigned* bitR0 = g_bits + (size_t)row0 * 128;
    const unsigned* bitR1 = bitR0 + 8 * 128;
    const uint4* attrP = g_attrP + head * (NN / 2);

    float acc[8][4], accz[4];
#pragma unroll
    for (int nt = 0; nt < 8; nt++)
#pragma unroll
        for (int q = 0; q < 4; q++) acc[nt][q] = 0.f;
#pragma unroll
    for (int q = 0; q < 4; q++) accz[q] = 0.f;

    uint32_t bz[2];
    bz[0] = bz[1] = (lane < 4) ? 0x3C003C00u : 0u;

    uint32_t bAddr = sb + (((lane & 7) + ((lane >> 4) & 1) * 8)) * (BSTR * 2)
                   + ((lane >> 3) & 1) * 16;

    auto stageB = [&](int j0, int bufn) {
        __half* Bd = (__half*)(sm + bufn * BBUF);
#pragma unroll
        for (int q = 0; q < 2; q++) {
            int lin = tid + q * 256;
            int f = lin >> 3, c = lin & 7;
            uint4 v = *(const uint4*)&g_WhT[(head * OF + f) * NN + j0 + c * 8];
            *(uint4*)&Bd[f * BSTR + c * 8] = v;
        }
    };

    const __half2 zero2 = __float2half2_rn(0.f);
    // val: masked gated product for one (row, j-pair)
    auto val = [&](int rowIdx, uint4 J, unsigned sel) -> uint32_t {
        __half2 dst2 = *(__half2*)&J.x;
        __half2 ed   = *(__half2*)&J.y;
        __half2 ed2  = *(__half2*)&J.z;
        unsigned g = __hgt2_mask(__hadd2(isrc[rowIdx], dst2), zero2);
        unsigned v = (h2u(__hmul2(ies[rowIdx], ed)) & g)
                   | (h2u(__hmul2(ies2[rowIdx], ed2)) & ~g);
        unsigned mask = (sel & 1u) * 0x0000FFFFu + (sel & 2u) * 0x7FFF8000u;
        return v & mask;
    };

    // generate A-fragments for step s1 into fr[4][4]
    auto genFrag = [&](int s1, uint32_t fr[4][4]) {
        uint2 bw0 = *(const uint2*)(bitR0 + s1 * 2);
        uint2 bw1 = *(const uint2*)(bitR1 + s1 * 2);
        const uint4* jp = attrP + (s1 << 5);
#pragma unroll
        for (int kc = 0; kc < 4; kc++) {
            uint4 JA = jp[kc * 8 + t];         // pair: j = s*64 + kc*16 + 2t
            uint4 JB = jp[kc * 8 + 4 + t];     // pair: j = s*64 + kc*16 + 8 + 2t
            unsigned w0 = (kc < 2) ? bw0.x : bw0.y;
            unsigned w1 = (kc < 2) ? bw1.x : bw1.y;
            int shA = ((kc & 1) << 4) + t2;
            fr[kc][0] = val(0, JA, (w0 >> shA) & 3u);
            fr[kc][1] = val(1, JA, (w1 >> shA) & 3u);
            fr[kc][2] = val(0, JB, (w0 >> (shA + 8)) & 3u);
            fr[kc][3] = val(1, JB, (w1 >> (shA + 8)) & 3u);
        }
    };

    uint32_t frag[2][4][4];
    stageB(0, 0);
    genFrag(0, frag[0]);

    for (int s = 0; s < 64; s++) {
        int buf = s & 1;
        __syncthreads();                 // B buf ready; buf^1 free for writes
        if (s < 63) stageB((s + 1) << 6, buf ^ 1);

#pragma unroll
        for (int kc = 0; kc < 4; kc++) {
            uint32_t b[16];
#pragma unroll
            for (int nq = 0; nq < 4; nq++)
                ldsm4(b[nq * 4], b[nq * 4 + 1], b[nq * 4 + 2], b[nq * 4 + 3],
                      bAddr + buf * BBUF + nq * 16 * (BSTR * 2) + kc * 32);
#pragma unroll
            for (int nt = 0; nt < 8; nt++)
                mma16816(acc[nt], frag[buf][kc], &b[nt * 2]);
            mma16816(accz, frag[buf][kc], bz);
        }

        if (s < 63) genFrag(s + 1, frag[buf ^ 1]);
    }

    // Z: accz col 0 on lanes t==0 (rows r, r+8); broadcast in row group
    float z0 = __shfl_sync(0xFFFFFFFFu, accz[0], lane & 28);
    float z1 = __shfl_sync(0xFFFFFFFFu, accz[2], lane & 28);
    float inv0 = 1.0f / z0;
    float inv1 = 1.0f / z1;

    {
        float* o0 = out + (size_t)row0 * CF + head * OF + t2;
        float* o1 = o0 + 8 * CF;
#pragma unroll
        for (int nt = 0; nt < 8; nt++) {
            float v0 = acc[nt][0] * inv0, v1 = acc[nt][1] * inv0;
            float v2 = acc[nt][2] * inv1, v3 = acc[nt][3] * inv1;
            v0 = v0 > 0.f ? v0 : (expf(v0) - 1.0f);
            v1 = v1 > 0.f ? v1 : (expf(v1) - 1.0f);
            v2 = v2 > 0.f ? v2 : (expf(v2) - 1.0f);
            v3 = v3 > 0.f ? v3 : (expf(v3) - 1.0f);
            *(float2*)(o0 + nt * 8) = make_float2(v0, v1);
            *(float2*)(o1 + nt * 8) = make_float2(v2, v3);
        }
    }
}

// ============================================================
extern "C" void kernel_launch(void* const* d_in, const int* in_sizes, int n_in,
                              void* d_out, int out_size) {
    const float* h   = (const float*)d_in[0];
    const int*   adj = (const int*)d_in[1];
    const float* W   = (const float*)d_in[2];
    const float* a   = (const float*)d_in[3];
    float* out = (float*)d_out;

    k_nop<<<1, 32>>>();
    k_cvtW<<<dim3(16, 16), 256>>>(W);
    k_ws<<<32, 256>>>(W, a);
    k_gemm16<<<dim3(8, 32), 256>>>(h);
    k_prep<<<NN, 256>>>(adj, h);

    cudaFuncSetAttribute(k_gat_mma, cudaFuncAttributeMaxDynamicSharedMemorySize, SM_TOT);
    k_gat_mma<<<dim3(NH, NN / 128), 256, SM_TOT>>>(out);
}